// round 1
// baseline (speedup 1.0000x reference)
#include <cuda_runtime.h>
#include <math.h>

// Problem constants
#define BATCH 2
#define SEQ   2048
#define DIM   4096
#define NHEAD 32
#define HDIM  128
#define MROWS (BATCH * SEQ)   // 4096

// Scratch (device globals; no allocation allowed in kernel_launch)
__device__ float g_q[BATCH * SEQ * DIM];
__device__ float g_k[BATCH * SEQ * DIM];
__device__ float g_v[BATCH * SEQ * DIM];
__device__ float g_attn[BATCH * SEQ * DIM];

// ---------------------------------------------------------------------------
// SGEMM (NT): C[M,N] = A[M,K] * B[N,K]^T   (both row-major, K-contiguous)
// 128x128 tile, BK=16, 256 threads, 8x8 micro-tile per thread.
// ---------------------------------------------------------------------------
__global__ __launch_bounds__(256) void sgemm_nt(const float* __restrict__ A,
                                                const float* __restrict__ B,
                                                float* __restrict__ C,
                                                int M, int N, int K) {
    __shared__ float As[16][128];
    __shared__ float Bs[16][128];

    const int tid = threadIdx.x;
    const int m0 = blockIdx.y * 128;
    const int n0 = blockIdx.x * 128;
    const int tx = tid & 15;
    const int ty = tid >> 4;

    // global load indices: each thread loads 2 float4 from A and 2 from B
    const int r0 = tid >> 2;          // 0..63
    const int c0 = (tid & 3) * 4;     // 0,4,8,12

    const float* Ap0 = A + (size_t)(m0 + r0) * K + c0;
    const float* Ap1 = A + (size_t)(m0 + r0 + 64) * K + c0;
    const float* Bp0 = B + (size_t)(n0 + r0) * K + c0;
    const float* Bp1 = B + (size_t)(n0 + r0 + 64) * K + c0;

    float acc[8][8];
#pragma unroll
    for (int i = 0; i < 8; i++)
#pragma unroll
        for (int j = 0; j < 8; j++) acc[i][j] = 0.0f;

    for (int k0 = 0; k0 < K; k0 += 16) {
        float4 a0 = *(const float4*)(Ap0 + k0);
        float4 a1 = *(const float4*)(Ap1 + k0);
        float4 b0 = *(const float4*)(Bp0 + k0);
        float4 b1 = *(const float4*)(Bp1 + k0);

        __syncthreads();  // previous tile's compute done before overwrite
        As[c0 + 0][r0] = a0.x; As[c0 + 1][r0] = a0.y;
        As[c0 + 2][r0] = a0.z; As[c0 + 3][r0] = a0.w;
        As[c0 + 0][r0 + 64] = a1.x; As[c0 + 1][r0 + 64] = a1.y;
        As[c0 + 2][r0 + 64] = a1.z; As[c0 + 3][r0 + 64] = a1.w;
        Bs[c0 + 0][r0] = b0.x; Bs[c0 + 1][r0] = b0.y;
        Bs[c0 + 2][r0] = b0.z; Bs[c0 + 3][r0] = b0.w;
        Bs[c0 + 0][r0 + 64] = b1.x; Bs[c0 + 1][r0 + 64] = b1.y;
        Bs[c0 + 2][r0 + 64] = b1.z; Bs[c0 + 3][r0 + 64] = b1.w;
        __syncthreads();

#pragma unroll
        for (int kk = 0; kk < 16; kk++) {
            float4 ra0 = *(const float4*)&As[kk][ty * 4];
            float4 ra1 = *(const float4*)&As[kk][64 + ty * 4];
            float4 rb0 = *(const float4*)&Bs[kk][tx * 4];
            float4 rb1 = *(const float4*)&Bs[kk][64 + tx * 4];
            float ra[8] = {ra0.x, ra0.y, ra0.z, ra0.w, ra1.x, ra1.y, ra1.z, ra1.w};
            float rb[8] = {rb0.x, rb0.y, rb0.z, rb0.w, rb1.x, rb1.y, rb1.z, rb1.w};
#pragma unroll
            for (int i = 0; i < 8; i++)
#pragma unroll
                for (int j = 0; j < 8; j++) acc[i][j] += ra[i] * rb[j];
        }
    }

#pragma unroll
    for (int i = 0; i < 8; i++) {
        int m = m0 + ((i < 4) ? (ty * 4 + i) : (64 + ty * 4 + (i - 4)));
        float* crow = C + (size_t)m * N + n0;
        float4 v0 = make_float4(acc[i][0], acc[i][1], acc[i][2], acc[i][3]);
        float4 v1 = make_float4(acc[i][4], acc[i][5], acc[i][6], acc[i][7]);
        *(float4*)(crow + tx * 4) = v0;
        *(float4*)(crow + 64 + tx * 4) = v1;
    }
}

// ---------------------------------------------------------------------------
// RoPE: interleaved pairs within each head. Applies to g_q and g_k in place.
// ---------------------------------------------------------------------------
__global__ void rope_kernel(const float* __restrict__ fcos,
                            const float* __restrict__ fsin) {
    int idx = blockIdx.x * blockDim.x + threadIdx.x;  // B*S*H*64 = 2^23
    int j = idx & 63;
    int h = (idx >> 6) & 31;
    int s = (idx >> 11) & 2047;
    int b = idx >> 22;

    float c = fcos[s * 64 + j];
    float sn = fsin[s * 64 + j];
    size_t base = ((size_t)(b * SEQ + s)) * DIM + h * HDIM + 2 * j;

    float qr = g_q[base], qi = g_q[base + 1];
    g_q[base]     = qr * c - qi * sn;
    g_q[base + 1] = qr * sn + qi * c;

    float kr = g_k[base], ki = g_k[base + 1];
    g_k[base]     = kr * c - ki * sn;
    g_k[base + 1] = kr * sn + ki * c;
}

// ---------------------------------------------------------------------------
// Flash attention (fp32, non-causal): per block one (b, h, 64-row q tile).
// 64x64 kv tiles, online softmax. 256 threads.
//   S tile: thread (ty,tx) owns rows {ty+16*ii}, cols {tx+16*jj}  (4x4)
//   O tile: same rows, cols {tx+16*jc}, jc<8                      (4x8)
// ---------------------------------------------------------------------------
#define KPITCH 132   // pad: 132 % 32 == 4 -> 2-way instead of 16-way conflicts
#define PPITCH 65

#define FLASH_SMEM_FLOATS (64 * 128 + 64 * KPITCH + 64 * 128 + 64 * PPITCH)

__global__ __launch_bounds__(256) void flash_kernel() {
    extern __shared__ float sm[];
    float* Qs = sm;                      // [64][128]
    float* Ks = Qs + 64 * 128;           // [64][KPITCH]
    float* Vs = Ks + 64 * KPITCH;        // [64][128]
    float* Ps = Vs + 64 * 128;           // [64][PPITCH]

    const int tid = threadIdx.x;
    const int qt = blockIdx.x;
    const int h  = blockIdx.y;
    const int b  = blockIdx.z;
    const int q0 = qt * 64;
    const int tx = tid & 15;
    const int ty = tid >> 4;
    const size_t hoff = (size_t)h * HDIM;
    const float scale = 0.08838834764831845f;  // 1/sqrt(128)

    // Load Q tile (scaled)
    for (int i = tid; i < 2048; i += 256) {  // 2048 float4
        int r = i >> 5;
        int c4 = (i & 31) * 4;
        float4 v = *(const float4*)(g_q + ((size_t)(b * SEQ + q0 + r)) * DIM + hoff + c4);
        v.x *= scale; v.y *= scale; v.z *= scale; v.w *= scale;
        *(float4*)(Qs + r * 128 + c4) = v;
    }

    float m_i[4], l_i[4], acc[4][8];
#pragma unroll
    for (int i = 0; i < 4; i++) {
        m_i[i] = -INFINITY;
        l_i[i] = 0.0f;
#pragma unroll
        for (int j = 0; j < 8; j++) acc[i][j] = 0.0f;
    }

    for (int j0 = 0; j0 < SEQ; j0 += 64) {
        __syncthreads();  // previous PV reads (and Qs load) complete
        // Load K, V tiles
        for (int i = tid; i < 2048; i += 256) {
            int r = i >> 5;
            int c4 = (i & 31) * 4;
            size_t g = ((size_t)(b * SEQ + j0 + r)) * DIM + hoff + c4;
            *(float4*)(Ks + r * KPITCH + c4) = *(const float4*)(g_k + g);
            *(float4*)(Vs + r * 128 + c4)    = *(const float4*)(g_v + g);
        }
        __syncthreads();

        // S = Q K^T  (4x4 per thread)
        float s4[4][4];
#pragma unroll
        for (int i = 0; i < 4; i++)
#pragma unroll
            for (int j = 0; j < 4; j++) s4[i][j] = 0.0f;

        for (int d = 0; d < 128; d += 4) {
            float4 q4[4], k4[4];
#pragma unroll
            for (int ii = 0; ii < 4; ii++)
                q4[ii] = *(const float4*)(Qs + (ty + 16 * ii) * 128 + d);
#pragma unroll
            for (int jj = 0; jj < 4; jj++)
                k4[jj] = *(const float4*)(Ks + (tx + 16 * jj) * KPITCH + d);
#pragma unroll
            for (int ii = 0; ii < 4; ii++)
#pragma unroll
                for (int jj = 0; jj < 4; jj++) {
                    s4[ii][jj] += q4[ii].x * k4[jj].x;
                    s4[ii][jj] += q4[ii].y * k4[jj].y;
                    s4[ii][jj] += q4[ii].z * k4[jj].z;
                    s4[ii][jj] += q4[ii].w * k4[jj].w;
                }
        }

        // Online softmax per owned row
#pragma unroll
        for (int ii = 0; ii < 4; ii++) {
            float mx = s4[ii][0];
#pragma unroll
            for (int jj = 1; jj < 4; jj++) mx = fmaxf(mx, s4[ii][jj]);
#pragma unroll
            for (int off = 8; off >= 1; off >>= 1)
                mx = fmaxf(mx, __shfl_xor_sync(0xffffffffu, mx, off));

            float mnew = fmaxf(m_i[ii], mx);
            float alpha = __expf(m_i[ii] - mnew);
            float rs = 0.0f;
            int row = ty + 16 * ii;
#pragma unroll
            for (int jj = 0; jj < 4; jj++) {
                float p = __expf(s4[ii][jj] - mnew);
                Ps[row * PPITCH + tx + 16 * jj] = p;
                rs += p;
            }
#pragma unroll
            for (int off = 8; off >= 1; off >>= 1)
                rs += __shfl_xor_sync(0xffffffffu, rs, off);

            l_i[ii] = l_i[ii] * alpha + rs;
            m_i[ii] = mnew;
#pragma unroll
            for (int jc = 0; jc < 8; jc++) acc[ii][jc] *= alpha;
        }
        __syncthreads();

        // O += P * V
        for (int kk = 0; kk < 64; kk++) {
            float pv[4], vv[8];
#pragma unroll
            for (int ii = 0; ii < 4; ii++)
                pv[ii] = Ps[(ty + 16 * ii) * PPITCH + kk];
#pragma unroll
            for (int jc = 0; jc < 8; jc++)
                vv[jc] = Vs[kk * 128 + tx + 16 * jc];
#pragma unroll
            for (int ii = 0; ii < 4; ii++)
#pragma unroll
                for (int jc = 0; jc < 8; jc++) acc[ii][jc] += pv[ii] * vv[jc];
        }
    }

    // Normalize and store
#pragma unroll
    for (int ii = 0; ii < 4; ii++) {
        float inv = 1.0f / l_i[ii];
        size_t base = ((size_t)(b * SEQ + q0 + ty + 16 * ii)) * DIM + hoff;
#pragma unroll
        for (int jc = 0; jc < 8; jc++)
            g_attn[base + tx + 16 * jc] = acc[ii][jc] * inv;
    }
}

// ---------------------------------------------------------------------------
// Launch
// ---------------------------------------------------------------------------
extern "C" void kernel_launch(void* const* d_in, const int* in_sizes, int n_in,
                              void* d_out, int out_size) {
    const float* x    = (const float*)d_in[0];
    const float* wq   = (const float*)d_in[1];
    const float* wk   = (const float*)d_in[2];
    const float* wv   = (const float*)d_in[3];
    const float* wo   = (const float*)d_in[4];
    const float* fcos = (const float*)d_in[5];
    const float* fsin = (const float*)d_in[6];
    // d_in[7] = start_pos (always 0 for this problem)
    float* out = (float*)d_out;

    float *qp, *kp, *vp, *ap;
    cudaGetSymbolAddress((void**)&qp, g_q);
    cudaGetSymbolAddress((void**)&kp, g_k);
    cudaGetSymbolAddress((void**)&vp, g_v);
    cudaGetSymbolAddress((void**)&ap, g_attn);

    dim3 gemm_grid(DIM / 128, MROWS / 128);

    sgemm_nt<<<gemm_grid, 256>>>(x, wq, qp, MROWS, DIM, DIM);
    sgemm_nt<<<gemm_grid, 256>>>(x, wk, kp, MROWS, DIM, DIM);
    sgemm_nt<<<gemm_grid, 256>>>(x, wv, vp, MROWS, DIM, DIM);

    rope_kernel<<<(BATCH * SEQ * NHEAD * 64) / 256, 256>>>(fcos, fsin);

    size_t flash_smem = FLASH_SMEM_FLOATS * sizeof(float);
    cudaFuncSetAttribute(flash_kernel,
                         cudaFuncAttributeMaxDynamicSharedMemorySize,
                         (int)flash_smem);
    flash_kernel<<<dim3(SEQ / 64, NHEAD, BATCH), 256, flash_smem>>>();

    sgemm_nt<<<gemm_grid, 256>>>(ap, wo, out, MROWS, DIM, DIM);
}

// round 3
// speedup vs baseline: 1.4833x; 1.4833x over previous
#include <cuda_runtime.h>
#include <cuda_bf16.h>
#include <math.h>
#include <stdint.h>

// Problem constants
#define BATCH 2
#define SEQ   2048
#define DIM   4096
#define NHEAD 32
#define HDIM  128
#define MROWS (BATCH * SEQ)   // 4096

// Scratch (device globals)
__device__ float g_q[BATCH * SEQ * DIM];
__device__ float g_k[BATCH * SEQ * DIM];
__device__ float g_v[BATCH * SEQ * DIM];
__device__ float g_attn[BATCH * SEQ * DIM];

// ---------------------------------------------------------------------------
// Helpers (baseline PTX only — no tcgen05; harness targets compute_103)
// ---------------------------------------------------------------------------
__device__ __forceinline__ uint32_t smem_u32(const void* p) {
    uint32_t a;
    asm("{ .reg .u64 t; cvta.to.shared.u64 t, %1; cvt.u32.u64 %0, t; }"
        : "=r"(a) : "l"(p));
    return a;
}

__device__ __forceinline__ void ldsm4(uint32_t addr, uint32_t& r0, uint32_t& r1,
                                      uint32_t& r2, uint32_t& r3) {
    asm volatile("ldmatrix.sync.aligned.m8n8.x4.shared.b16 {%0,%1,%2,%3}, [%4];"
                 : "=r"(r0), "=r"(r1), "=r"(r2), "=r"(r3) : "r"(addr));
}

__device__ __forceinline__ void mma_bf16(float* c, const uint32_t* a,
                                         const uint32_t* b) {
    asm volatile(
        "mma.sync.aligned.m16n8k16.row.col.f32.bf16.bf16.f32 "
        "{%0,%1,%2,%3}, {%4,%5,%6,%7}, {%8,%9}, {%0,%1,%2,%3};"
        : "+f"(c[0]), "+f"(c[1]), "+f"(c[2]), "+f"(c[3])
        : "r"(a[0]), "r"(a[1]), "r"(a[2]), "r"(a[3]), "r"(b[0]), "r"(b[1]));
}

__device__ __forceinline__ uint32_t packbf(__nv_bfloat16 a, __nv_bfloat16 b) {
    return ((uint32_t)__bfloat16_as_ushort(b) << 16) | __bfloat16_as_ushort(a);
}

// ---------------------------------------------------------------------------
// bf16x3-split GEMM (NT): C[M,N] = A[M,K] * B[N,K]^T, M=N=K=4096, fp32 in/out.
// 128x128 tile, BK=32, 256 threads (8 warps as 2x4), warp tile 64x32.
// Smem tiles [rows][32] bf16, row pitch 80 B (conflict-free ldmatrix).
// ---------------------------------------------------------------------------
#define BM 128
#define BN 128
#define BK 32
#define NKC (DIM / BK)   // 128
#define PITCHB 80        // bytes per smem tile row

#define OFF_AHI 0
#define OFF_ALO 10240
#define OFF_BHI 20480
#define OFF_BLO 30720
#define STAGE_BYTES 40960
#define GEMM_SMEM (2 * STAGE_BYTES)   // 81920

__global__ __launch_bounds__(256, 1)
void gemm_bf16x3(const float* __restrict__ A, const float* __restrict__ B,
                 float* __restrict__ C) {
    extern __shared__ char smem_raw[];
    const uint32_t sbase = smem_u32(smem_raw);
    const int tid  = threadIdx.x;
    const int wid  = tid >> 5;
    const int lane = tid & 31;
    const int wm   = wid >> 2;        // 0..1
    const int wn   = wid & 3;         // 0..3
    const int m0   = blockIdx.y * BM;
    const int n0   = blockIdx.x * BN;

    float acc[4][4][4];
#pragma unroll
    for (int i = 0; i < 4; i++)
#pragma unroll
        for (int j = 0; j < 4; j++)
#pragma unroll
            for (int k = 0; k < 4; k++) acc[i][j][k] = 0.0f;

    // staging registers: 4 float4 from A, 4 from B per chunk
    float4 aReg[4], bReg[4];
    const int r_ld = tid >> 3;          // base row for it=0 (0..31)
    const int f_ld = tid & 7;           // float4 index within row

    const float* Abase = A + (size_t)(m0 + r_ld) * DIM + f_ld * 4;
    const float* Bbase = B + (size_t)(n0 + r_ld) * DIM + f_ld * 4;

#define LOAD_CHUNK(kc)                                                        \
    {                                                                         \
        const float* ap = Abase + (kc) * BK;                                  \
        const float* bp = Bbase + (kc) * BK;                                  \
        _Pragma("unroll")                                                     \
        for (int it = 0; it < 4; it++) {                                      \
            aReg[it] = *(const float4*)(ap + (size_t)(32 * it) * DIM);        \
            bReg[it] = *(const float4*)(bp + (size_t)(32 * it) * DIM);        \
        }                                                                     \
    }

#define STORE_CHUNK(stg_c)                                                    \
    {                                                                         \
        char* sp = smem_raw + (stg_c) * STAGE_BYTES;                          \
        _Pragma("unroll")                                                     \
        for (int it = 0; it < 4; it++) {                                      \
            int r = r_ld + 32 * it;                                           \
            uint32_t off = (uint32_t)r * PITCHB + f_ld * 8;                   \
            float4 v = aReg[it];                                              \
            __nv_bfloat16 hx = __float2bfloat16(v.x);                         \
            __nv_bfloat16 hy = __float2bfloat16(v.y);                         \
            __nv_bfloat16 hz = __float2bfloat16(v.z);                         \
            __nv_bfloat16 hw = __float2bfloat16(v.w);                         \
            __nv_bfloat16 lx = __float2bfloat16(v.x - __bfloat162float(hx));  \
            __nv_bfloat16 ly = __float2bfloat16(v.y - __bfloat162float(hy));  \
            __nv_bfloat16 lz = __float2bfloat16(v.z - __bfloat162float(hz));  \
            __nv_bfloat16 lw = __float2bfloat16(v.w - __bfloat162float(hw));  \
            *(uint2*)(sp + OFF_AHI + off) =                                   \
                make_uint2(packbf(hx, hy), packbf(hz, hw));                   \
            *(uint2*)(sp + OFF_ALO + off) =                                   \
                make_uint2(packbf(lx, ly), packbf(lz, lw));                   \
            v = bReg[it];                                                     \
            hx = __float2bfloat16(v.x); hy = __float2bfloat16(v.y);           \
            hz = __float2bfloat16(v.z); hw = __float2bfloat16(v.w);           \
            lx = __float2bfloat16(v.x - __bfloat162float(hx));                \
            ly = __float2bfloat16(v.y - __bfloat162float(hy));                \
            lz = __float2bfloat16(v.z - __bfloat162float(hz));                \
            lw = __float2bfloat16(v.w - __bfloat162float(hw));                \
            *(uint2*)(sp + OFF_BHI + off) =                                   \
                make_uint2(packbf(hx, hy), packbf(hz, hw));                   \
            *(uint2*)(sp + OFF_BLO + off) =                                   \
                make_uint2(packbf(lx, ly), packbf(lz, lw));                   \
        }                                                                     \
    }

    // ldmatrix lane addressing: row = lane&15, k-half = (lane>>4)*16 bytes
    const uint32_t lm_off = (uint32_t)(lane & 15) * PITCHB + (lane >> 4) * 16;
    const uint32_t aAdr0 = (uint32_t)(wm * 64) * PITCHB + lm_off;  // + OFF_AHI
    const uint32_t bAdr0 = (uint32_t)(wn * 32) * PITCHB + lm_off;  // + OFF_BHI

    // Prologue
    LOAD_CHUNK(0);
    STORE_CHUNK(0);
    __syncthreads();

    for (int kc = 0; kc < NKC; kc++) {
        const int cur = kc & 1;
        if (kc + 1 < NKC) LOAD_CHUNK(kc + 1);

        const uint32_t stg = sbase + (uint32_t)cur * STAGE_BYTES;
        const uint32_t aHi = stg + OFF_AHI + aAdr0;
        const uint32_t aLo = stg + OFF_ALO + aAdr0;
        const uint32_t bHi = stg + OFF_BHI + bAdr0;
        const uint32_t bLo = stg + OFF_BLO + bAdr0;

#pragma unroll
        for (int s = 0; s < 2; s++) {
            uint32_t aF[4][4], bH[4][2], bL[4][2];
#pragma unroll
            for (int mi = 0; mi < 4; mi++)
                ldsm4(aHi + mi * (16 * PITCHB) + s * 32,
                      aF[mi][0], aF[mi][1], aF[mi][2], aF[mi][3]);
#pragma unroll
            for (int nj = 0; nj < 2; nj++) {
                uint32_t r0, r1, r2, r3;
                ldsm4(bHi + nj * (16 * PITCHB) + s * 32, r0, r1, r2, r3);
                bH[nj * 2][0] = r0; bH[nj * 2 + 1][0] = r1;
                bH[nj * 2][1] = r2; bH[nj * 2 + 1][1] = r3;
                ldsm4(bLo + nj * (16 * PITCHB) + s * 32, r0, r1, r2, r3);
                bL[nj * 2][0] = r0; bL[nj * 2 + 1][0] = r1;
                bL[nj * 2][1] = r2; bL[nj * 2 + 1][1] = r3;
            }
            // pass hh
#pragma unroll
            for (int mi = 0; mi < 4; mi++)
#pragma unroll
                for (int nf = 0; nf < 4; nf++)
                    mma_bf16(acc[mi][nf], aF[mi], bH[nf]);
            // pass hl
#pragma unroll
            for (int mi = 0; mi < 4; mi++)
#pragma unroll
                for (int nf = 0; nf < 4; nf++)
                    mma_bf16(acc[mi][nf], aF[mi], bL[nf]);
            // pass lh: reload A-lo frags
#pragma unroll
            for (int mi = 0; mi < 4; mi++)
                ldsm4(aLo + mi * (16 * PITCHB) + s * 32,
                      aF[mi][0], aF[mi][1], aF[mi][2], aF[mi][3]);
#pragma unroll
            for (int mi = 0; mi < 4; mi++)
#pragma unroll
                for (int nf = 0; nf < 4; nf++)
                    mma_bf16(acc[mi][nf], aF[mi], bH[nf]);
        }

        __syncthreads();            // all warps done reading stage cur
        if (kc + 1 < NKC) {
            STORE_CHUNK(1 - cur);
            __syncthreads();        // next stage visible to all
        }
    }

    // Epilogue: direct stores (float2 per frag-row; 32B sectors fully used)
#pragma unroll
    for (int mi = 0; mi < 4; mi++) {
#pragma unroll
        for (int nf = 0; nf < 4; nf++) {
            int row = m0 + wm * 64 + mi * 16 + (lane >> 2);
            int col = n0 + wn * 32 + nf * 8 + (lane & 3) * 2;
            *(float2*)&C[(size_t)row * DIM + col] =
                make_float2(acc[mi][nf][0], acc[mi][nf][1]);
            *(float2*)&C[(size_t)(row + 8) * DIM + col] =
                make_float2(acc[mi][nf][2], acc[mi][nf][3]);
        }
    }
#undef LOAD_CHUNK
#undef STORE_CHUNK
}

// ---------------------------------------------------------------------------
// RoPE (unchanged)
// ---------------------------------------------------------------------------
__global__ void rope_kernel(const float* __restrict__ fcos,
                            const float* __restrict__ fsin) {
    int idx = blockIdx.x * blockDim.x + threadIdx.x;
    int j = idx & 63;
    int h = (idx >> 6) & 31;
    int s = (idx >> 11) & 2047;
    int b = idx >> 22;

    float c = fcos[s * 64 + j];
    float sn = fsin[s * 64 + j];
    size_t base = ((size_t)(b * SEQ + s)) * DIM + h * HDIM + 2 * j;

    float qr = g_q[base], qi = g_q[base + 1];
    g_q[base]     = qr * c - qi * sn;
    g_q[base + 1] = qr * sn + qi * c;

    float kr = g_k[base], ki = g_k[base + 1];
    g_k[base]     = kr * c - ki * sn;
    g_k[base + 1] = kr * sn + ki * c;
}

// ---------------------------------------------------------------------------
// Flash attention (fp32, unchanged from R1 — passed with rel_err 3.6e-6)
// ---------------------------------------------------------------------------
#define KPITCH 132
#define PPITCH 65
#define FLASH_SMEM_FLOATS (64 * 128 + 64 * KPITCH + 64 * 128 + 64 * PPITCH)

__global__ __launch_bounds__(256) void flash_kernel() {
    extern __shared__ float sm[];
    float* Qs = sm;
    float* Ks = Qs + 64 * 128;
    float* Vs = Ks + 64 * KPITCH;
    float* Ps = Vs + 64 * 128;

    const int tid = threadIdx.x;
    const int qt = blockIdx.x;
    const int h  = blockIdx.y;
    const int b  = blockIdx.z;
    const int q0 = qt * 64;
    const int tx = tid & 15;
    const int ty = tid >> 4;
    const size_t hoff = (size_t)h * HDIM;
    const float scale = 0.08838834764831845f;

    for (int i = tid; i < 2048; i += 256) {
        int r = i >> 5;
        int c4 = (i & 31) * 4;
        float4 v = *(const float4*)(g_q + ((size_t)(b * SEQ + q0 + r)) * DIM + hoff + c4);
        v.x *= scale; v.y *= scale; v.z *= scale; v.w *= scale;
        *(float4*)(Qs + r * 128 + c4) = v;
    }

    float m_i[4], l_i[4], acc[4][8];
#pragma unroll
    for (int i = 0; i < 4; i++) {
        m_i[i] = -INFINITY;
        l_i[i] = 0.0f;
#pragma unroll
        for (int j = 0; j < 8; j++) acc[i][j] = 0.0f;
    }

    for (int j0 = 0; j0 < SEQ; j0 += 64) {
        __syncthreads();
        for (int i = tid; i < 2048; i += 256) {
            int r = i >> 5;
            int c4 = (i & 31) * 4;
            size_t g = ((size_t)(b * SEQ + j0 + r)) * DIM + hoff + c4;
            *(float4*)(Ks + r * KPITCH + c4) = *(const float4*)(g_k + g);
            *(float4*)(Vs + r * 128 + c4)    = *(const float4*)(g_v + g);
        }
        __syncthreads();

        float s4[4][4];
#pragma unroll
        for (int i = 0; i < 4; i++)
#pragma unroll
            for (int j = 0; j < 4; j++) s4[i][j] = 0.0f;

        for (int d = 0; d < 128; d += 4) {
            float4 q4[4], k4[4];
#pragma unroll
            for (int ii = 0; ii < 4; ii++)
                q4[ii] = *(const float4*)(Qs + (ty + 16 * ii) * 128 + d);
#pragma unroll
            for (int jj = 0; jj < 4; jj++)
                k4[jj] = *(const float4*)(Ks + (tx + 16 * jj) * KPITCH + d);
#pragma unroll
            for (int ii = 0; ii < 4; ii++)
#pragma unroll
                for (int jj = 0; jj < 4; jj++) {
                    s4[ii][jj] += q4[ii].x * k4[jj].x;
                    s4[ii][jj] += q4[ii].y * k4[jj].y;
                    s4[ii][jj] += q4[ii].z * k4[jj].z;
                    s4[ii][jj] += q4[ii].w * k4[jj].w;
                }
        }

#pragma unroll
        for (int ii = 0; ii < 4; ii++) {
            float mx = s4[ii][0];
#pragma unroll
            for (int jj = 1; jj < 4; jj++) mx = fmaxf(mx, s4[ii][jj]);
#pragma unroll
            for (int off = 8; off >= 1; off >>= 1)
                mx = fmaxf(mx, __shfl_xor_sync(0xffffffffu, mx, off));

            float mnew = fmaxf(m_i[ii], mx);
            float alpha = __expf(m_i[ii] - mnew);
            float rs = 0.0f;
            int row = ty + 16 * ii;
#pragma unroll
            for (int jj = 0; jj < 4; jj++) {
                float p = __expf(s4[ii][jj] - mnew);
                Ps[row * PPITCH + tx + 16 * jj] = p;
                rs += p;
            }
#pragma unroll
            for (int off = 8; off >= 1; off >>= 1)
                rs += __shfl_xor_sync(0xffffffffu, rs, off);

            l_i[ii] = l_i[ii] * alpha + rs;
            m_i[ii] = mnew;
#pragma unroll
            for (int jc = 0; jc < 8; jc++) acc[ii][jc] *= alpha;
        }
        __syncthreads();

        for (int kk = 0; kk < 64; kk++) {
            float pv[4], vv[8];
#pragma unroll
            for (int ii = 0; ii < 4; ii++)
                pv[ii] = Ps[(ty + 16 * ii) * PPITCH + kk];
#pragma unroll
            for (int jc = 0; jc < 8; jc++)
                vv[jc] = Vs[kk * 128 + tx + 16 * jc];
#pragma unroll
            for (int ii = 0; ii < 4; ii++)
#pragma unroll
                for (int jc = 0; jc < 8; jc++) acc[ii][jc] += pv[ii] * vv[jc];
        }
    }

#pragma unroll
    for (int ii = 0; ii < 4; ii++) {
        float inv = 1.0f / l_i[ii];
        size_t base = ((size_t)(b * SEQ + q0 + ty + 16 * ii)) * DIM + hoff;
#pragma unroll
        for (int jc = 0; jc < 8; jc++)
            g_attn[base + tx + 16 * jc] = acc[ii][jc] * inv;
    }
}

// ---------------------------------------------------------------------------
// Launch
// ---------------------------------------------------------------------------
extern "C" void kernel_launch(void* const* d_in, const int* in_sizes, int n_in,
                              void* d_out, int out_size) {
    const float* x    = (const float*)d_in[0];
    const float* wq   = (const float*)d_in[1];
    const float* wk   = (const float*)d_in[2];
    const float* wv   = (const float*)d_in[3];
    const float* wo   = (const float*)d_in[4];
    const float* fcos = (const float*)d_in[5];
    const float* fsin = (const float*)d_in[6];
    float* out = (float*)d_out;

    float *qp, *kp, *vp, *ap;
    cudaGetSymbolAddress((void**)&qp, g_q);
    cudaGetSymbolAddress((void**)&kp, g_k);
    cudaGetSymbolAddress((void**)&vp, g_v);
    cudaGetSymbolAddress((void**)&ap, g_attn);

    cudaFuncSetAttribute(gemm_bf16x3, cudaFuncAttributeMaxDynamicSharedMemorySize,
                         GEMM_SMEM);
    cudaFuncSetAttribute(flash_kernel, cudaFuncAttributeMaxDynamicSharedMemorySize,
                         (int)(FLASH_SMEM_FLOATS * sizeof(float)));

    dim3 ggrid(DIM / BN, MROWS / BM);   // (32, 32)

    gemm_bf16x3<<<ggrid, 256, GEMM_SMEM>>>(x, wq, qp);
    gemm_bf16x3<<<ggrid, 256, GEMM_SMEM>>>(x, wk, kp);
    gemm_bf16x3<<<ggrid, 256, GEMM_SMEM>>>(x, wv, vp);

    rope_kernel<<<(BATCH * SEQ * NHEAD * 64) / 256, 256>>>(fcos, fsin);

    size_t flash_smem = FLASH_SMEM_FLOATS * sizeof(float);
    flash_kernel<<<dim3(SEQ / 64, NHEAD, BATCH), 256, flash_smem>>>();

    gemm_bf16x3<<<ggrid, 256, GEMM_SMEM>>>(ap, wo, out);
}

// round 4
// speedup vs baseline: 1.9907x; 1.3421x over previous
#include <cuda_runtime.h>
#include <cuda_bf16.h>
#include <math.h>
#include <stdint.h>

// Problem constants
#define BATCH 2
#define SEQ   2048
#define DIM   4096
#define NHEAD 32
#define HDIM  128
#define MROWS (BATCH * SEQ)   // 4096

// Scratch (device globals)
__device__ float g_q[BATCH * SEQ * DIM];
__device__ float g_k[BATCH * SEQ * DIM];
__device__ float g_v[BATCH * SEQ * DIM];
__device__ float g_attn[BATCH * SEQ * DIM];

// ---------------------------------------------------------------------------
// Helpers (baseline PTX only — harness targets compute_103, no tcgen05)
// ---------------------------------------------------------------------------
__device__ __forceinline__ uint32_t smem_u32(const void* p) {
    uint32_t a;
    asm("{ .reg .u64 t; cvta.to.shared.u64 t, %1; cvt.u32.u64 %0, t; }"
        : "=r"(a) : "l"(p));
    return a;
}

__device__ __forceinline__ void ldsm4(uint32_t addr, uint32_t& r0, uint32_t& r1,
                                      uint32_t& r2, uint32_t& r3) {
    asm volatile("ldmatrix.sync.aligned.m8n8.x4.shared.b16 {%0,%1,%2,%3}, [%4];"
                 : "=r"(r0), "=r"(r1), "=r"(r2), "=r"(r3) : "r"(addr));
}

__device__ __forceinline__ void ldsm4t(uint32_t addr, uint32_t& r0, uint32_t& r1,
                                       uint32_t& r2, uint32_t& r3) {
    asm volatile("ldmatrix.sync.aligned.m8n8.x4.trans.shared.b16 {%0,%1,%2,%3}, [%4];"
                 : "=r"(r0), "=r"(r1), "=r"(r2), "=r"(r3) : "r"(addr));
}

__device__ __forceinline__ void mma_bf16(float* c, const uint32_t* a,
                                         const uint32_t* b) {
    asm volatile(
        "mma.sync.aligned.m16n8k16.row.col.f32.bf16.bf16.f32 "
        "{%0,%1,%2,%3}, {%4,%5,%6,%7}, {%8,%9}, {%0,%1,%2,%3};"
        : "+f"(c[0]), "+f"(c[1]), "+f"(c[2]), "+f"(c[3])
        : "r"(a[0]), "r"(a[1]), "r"(a[2]), "r"(a[3]), "r"(b[0]), "r"(b[1]));
}

__device__ __forceinline__ void mma_bf16_2(float* c, const uint32_t* a,
                                           uint32_t b0, uint32_t b1) {
    asm volatile(
        "mma.sync.aligned.m16n8k16.row.col.f32.bf16.bf16.f32 "
        "{%0,%1,%2,%3}, {%4,%5,%6,%7}, {%8,%9}, {%0,%1,%2,%3};"
        : "+f"(c[0]), "+f"(c[1]), "+f"(c[2]), "+f"(c[3])
        : "r"(a[0]), "r"(a[1]), "r"(a[2]), "r"(a[3]), "r"(b0), "r"(b1));
}

__device__ __forceinline__ uint32_t packbf(__nv_bfloat16 a, __nv_bfloat16 b) {
    return ((uint32_t)__bfloat16_as_ushort(b) << 16) | __bfloat16_as_ushort(a);
}

// split pair of floats into (hi bf16x2, lo bf16x2)
__device__ __forceinline__ void split2(float x, float y, uint32_t& hi, uint32_t& lo) {
    __nv_bfloat16 hx = __float2bfloat16(x);
    __nv_bfloat16 hy = __float2bfloat16(y);
    hi = packbf(hx, hy);
    lo = packbf(__float2bfloat16(x - __bfloat162float(hx)),
                __float2bfloat16(y - __bfloat162float(hy)));
}

// ---------------------------------------------------------------------------
// bf16x3-split GEMM (NT): C[M,N] = A[M,K] * B[N,K]^T, fp32 in/out.
// 128x128 tile, BK=32, 256 threads (8 warps 2x4), warp tile 64x32.
// R4 change: ONE __syncthreads per K-chunk.
// ---------------------------------------------------------------------------
#define BM 128
#define BN 128
#define BK 32
#define NKC (DIM / BK)   // 128
#define PITCHB 80        // bytes per smem tile row

#define OFF_AHI 0
#define OFF_ALO 10240
#define OFF_BHI 20480
#define OFF_BLO 30720
#define STAGE_BYTES 40960
#define GEMM_SMEM (2 * STAGE_BYTES)   // 81920

__global__ __launch_bounds__(256, 1)
void gemm_bf16x3(const float* __restrict__ A, const float* __restrict__ B,
                 float* __restrict__ C) {
    extern __shared__ char smem_raw[];
    const uint32_t sbase = smem_u32(smem_raw);
    const int tid  = threadIdx.x;
    const int wid  = tid >> 5;
    const int lane = tid & 31;
    const int wm   = wid >> 2;
    const int wn   = wid & 3;
    const int m0   = blockIdx.y * BM;
    const int n0   = blockIdx.x * BN;

    float acc[4][4][4];
#pragma unroll
    for (int i = 0; i < 4; i++)
#pragma unroll
        for (int j = 0; j < 4; j++)
#pragma unroll
            for (int k = 0; k < 4; k++) acc[i][j][k] = 0.0f;

    float4 aReg[4], bReg[4];
    const int r_ld = tid >> 3;
    const int f_ld = tid & 7;

    const float* Abase = A + (size_t)(m0 + r_ld) * DIM + f_ld * 4;
    const float* Bbase = B + (size_t)(n0 + r_ld) * DIM + f_ld * 4;

#define LOAD_CHUNK(kc)                                                        \
    {                                                                         \
        const float* ap = Abase + (kc) * BK;                                  \
        const float* bp = Bbase + (kc) * BK;                                  \
        _Pragma("unroll")                                                     \
        for (int it = 0; it < 4; it++) {                                      \
            aReg[it] = *(const float4*)(ap + (size_t)(32 * it) * DIM);        \
            bReg[it] = *(const float4*)(bp + (size_t)(32 * it) * DIM);        \
        }                                                                     \
    }

#define STORE_CHUNK(stg_c)                                                    \
    {                                                                         \
        char* sp = smem_raw + (stg_c) * STAGE_BYTES;                          \
        _Pragma("unroll")                                                     \
        for (int it = 0; it < 4; it++) {                                      \
            int r = r_ld + 32 * it;                                           \
            uint32_t off = (uint32_t)r * PITCHB + f_ld * 8;                   \
            uint32_t h0, l0, h1, l1;                                          \
            split2(aReg[it].x, aReg[it].y, h0, l0);                           \
            split2(aReg[it].z, aReg[it].w, h1, l1);                           \
            *(uint2*)(sp + OFF_AHI + off) = make_uint2(h0, h1);               \
            *(uint2*)(sp + OFF_ALO + off) = make_uint2(l0, l1);               \
            split2(bReg[it].x, bReg[it].y, h0, l0);                           \
            split2(bReg[it].z, bReg[it].w, h1, l1);                           \
            *(uint2*)(sp + OFF_BHI + off) = make_uint2(h0, h1);               \
            *(uint2*)(sp + OFF_BLO + off) = make_uint2(l0, l1);               \
        }                                                                     \
    }

    const uint32_t lm_off = (uint32_t)(lane & 15) * PITCHB + (lane >> 4) * 16;
    const uint32_t aAdr0 = (uint32_t)(wm * 64) * PITCHB + lm_off;
    const uint32_t bAdr0 = (uint32_t)(wn * 32) * PITCHB + lm_off;

    LOAD_CHUNK(0);
    STORE_CHUNK(0);
    __syncthreads();

    for (int kc = 0; kc < NKC; kc++) {
        const int cur = kc & 1;
        if (kc + 1 < NKC) LOAD_CHUNK(kc + 1);

        const uint32_t stg = sbase + (uint32_t)cur * STAGE_BYTES;
        const uint32_t aHi = stg + OFF_AHI + aAdr0;
        const uint32_t aLo = stg + OFF_ALO + aAdr0;
        const uint32_t bHi = stg + OFF_BHI + bAdr0;
        const uint32_t bLo = stg + OFF_BLO + bAdr0;

#pragma unroll
        for (int s = 0; s < 2; s++) {
            uint32_t aF[4][4], bH[4][2], bL[4][2];
#pragma unroll
            for (int mi = 0; mi < 4; mi++)
                ldsm4(aHi + mi * (16 * PITCHB) + s * 32,
                      aF[mi][0], aF[mi][1], aF[mi][2], aF[mi][3]);
#pragma unroll
            for (int nj = 0; nj < 2; nj++) {
                uint32_t r0, r1, r2, r3;
                ldsm4(bHi + nj * (16 * PITCHB) + s * 32, r0, r1, r2, r3);
                bH[nj * 2][0] = r0; bH[nj * 2 + 1][0] = r1;
                bH[nj * 2][1] = r2; bH[nj * 2 + 1][1] = r3;
                ldsm4(bLo + nj * (16 * PITCHB) + s * 32, r0, r1, r2, r3);
                bL[nj * 2][0] = r0; bL[nj * 2 + 1][0] = r1;
                bL[nj * 2][1] = r2; bL[nj * 2 + 1][1] = r3;
            }
#pragma unroll
            for (int mi = 0; mi < 4; mi++)
#pragma unroll
                for (int nf = 0; nf < 4; nf++)
                    mma_bf16(acc[mi][nf], aF[mi], bH[nf]);
#pragma unroll
            for (int mi = 0; mi < 4; mi++)
#pragma unroll
                for (int nf = 0; nf < 4; nf++)
                    mma_bf16(acc[mi][nf], aF[mi], bL[nf]);
#pragma unroll
            for (int mi = 0; mi < 4; mi++)
                ldsm4(aLo + mi * (16 * PITCHB) + s * 32,
                      aF[mi][0], aF[mi][1], aF[mi][2], aF[mi][3]);
#pragma unroll
            for (int mi = 0; mi < 4; mi++)
#pragma unroll
                for (int nf = 0; nf < 4; nf++)
                    mma_bf16(acc[mi][nf], aF[mi], bH[nf]);
        }

        if (kc + 1 < NKC) STORE_CHUNK(1 - cur);
        __syncthreads();
    }

#pragma unroll
    for (int mi = 0; mi < 4; mi++) {
#pragma unroll
        for (int nf = 0; nf < 4; nf++) {
            int row = m0 + wm * 64 + mi * 16 + (lane >> 2);
            int col = n0 + wn * 32 + nf * 8 + (lane & 3) * 2;
            *(float2*)&C[(size_t)row * DIM + col] =
                make_float2(acc[mi][nf][0], acc[mi][nf][1]);
            *(float2*)&C[(size_t)(row + 8) * DIM + col] =
                make_float2(acc[mi][nf][2], acc[mi][nf][3]);
        }
    }
#undef LOAD_CHUNK
#undef STORE_CHUNK
}

// ---------------------------------------------------------------------------
// RoPE (unchanged)
// ---------------------------------------------------------------------------
__global__ void rope_kernel(const float* __restrict__ fcos,
                            const float* __restrict__ fsin) {
    int idx = blockIdx.x * blockDim.x + threadIdx.x;
    int j = idx & 63;
    int h = (idx >> 6) & 31;
    int s = (idx >> 11) & 2047;
    int b = idx >> 22;

    float c = fcos[s * 64 + j];
    float sn = fsin[s * 64 + j];
    size_t base = ((size_t)(b * SEQ + s)) * DIM + h * HDIM + 2 * j;

    float qr = g_q[base], qi = g_q[base + 1];
    g_q[base]     = qr * c - qi * sn;
    g_q[base + 1] = qr * sn + qi * c;

    float kr = g_k[base], ki = g_k[base + 1];
    g_k[base]     = kr * c - ki * sn;
    g_k[base + 1] = kr * sn + ki * c;
}

// ---------------------------------------------------------------------------
// Flash attention, tensor-core version (bf16x3 QK^T, bf16x3 PV).
// CTA: 128 q-rows of one (b,h); 8 warps x 16 q-rows. KV tiles of 64, double-
// buffered. Q staged in smem (hi/lo) once. Softmax in fp32 on C-fragments.
// ---------------------------------------------------------------------------
#define FPITCH 272              // smem row pitch (bytes) for 128-col bf16 rows
#define FQH 0                   // Q hi: 128 rows
#define FQL (128 * FPITCH)      // Q lo: 128 rows
#define FSTG0 (2 * 128 * FPITCH)
#define FKH 0                   // within stage: K hi (64 rows)
#define FKL (64 * FPITCH)
#define FVH (128 * FPITCH)
#define FVL (192 * FPITCH)
#define FSTAGE (256 * FPITCH)   // 69632 bytes per stage
#define FLASH_SMEM (FSTG0 + 2 * FSTAGE)   // 208896 bytes

__global__ __launch_bounds__(256)
void flash_mma() {
    extern __shared__ char smem_raw[];
    const uint32_t sbase = smem_u32(smem_raw);
    const int tid  = threadIdx.x;
    const int w    = tid >> 5;
    const int lane = tid & 31;
    const int qt = blockIdx.x;
    const int h  = blockIdx.y;
    const int b  = blockIdx.z;
    const int q0 = qt * 128;
    const size_t hoff = (size_t)h * HDIM;
    const float scale = 0.08838834764831845f;  // 1/sqrt(128)

    // ---- Stage Q (scaled, split hi/lo) ----
    for (int i = tid; i < 4096; i += 256) {
        int r = i >> 5;
        int c4 = (i & 31) * 4;
        float4 v = *(const float4*)(g_q + ((size_t)(b * SEQ + q0 + r)) * DIM + hoff + c4);
        v.x *= scale; v.y *= scale; v.z *= scale; v.w *= scale;
        uint32_t h0, l0, h1, l1;
        split2(v.x, v.y, h0, l0);
        split2(v.z, v.w, h1, l1);
        uint32_t off = (uint32_t)r * FPITCH + c4 * 2;
        *(uint2*)(smem_raw + FQH + off) = make_uint2(h0, h1);
        *(uint2*)(smem_raw + FQL + off) = make_uint2(l0, l1);
    }

    // ---- KV tile loader (fp32 global -> split bf16 smem) ----
#define LOADKV(t, stg)                                                        \
    {                                                                         \
        char* sp = smem_raw + FSTG0 + (stg) * FSTAGE;                         \
        const int j0 = (t) * 64;                                              \
        for (int i = tid; i < 2048; i += 256) {                               \
            int r = i >> 5;                                                   \
            int c4 = (i & 31) * 4;                                            \
            size_t g = ((size_t)(b * SEQ + j0 + r)) * DIM + hoff + c4;        \
            uint32_t off = (uint32_t)r * FPITCH + c4 * 2;                     \
            float4 kv = *(const float4*)(g_k + g);                            \
            float4 vv = *(const float4*)(g_v + g);                            \
            uint32_t h0, l0, h1, l1;                                          \
            split2(kv.x, kv.y, h0, l0);                                       \
            split2(kv.z, kv.w, h1, l1);                                       \
            *(uint2*)(sp + FKH + off) = make_uint2(h0, h1);                   \
            *(uint2*)(sp + FKL + off) = make_uint2(l0, l1);                   \
            split2(vv.x, vv.y, h0, l0);                                       \
            split2(vv.z, vv.w, h1, l1);                                       \
            *(uint2*)(sp + FVH + off) = make_uint2(h0, h1);                   \
            *(uint2*)(sp + FVL + off) = make_uint2(l0, l1);                   \
        }                                                                     \
    }

    LOADKV(0, 0);
    __syncthreads();

    // per-lane state: rows g = lane>>2 and g+8 within the warp's 16 rows
    float o[16][4];
#pragma unroll
    for (int nf = 0; nf < 16; nf++)
#pragma unroll
        for (int k = 0; k < 4; k++) o[nf][k] = 0.0f;
    float m0 = -INFINITY, m1 = -INFINITY, l0s = 0.0f, l1s = 0.0f;

    // ldmatrix address components
    const uint32_t lmA = (uint32_t)(lane & 15) * FPITCH + (lane >> 4) * 16;
    const uint32_t qAdr = sbase + (uint32_t)(w * 16) * FPITCH + lmA;  // +FQH/FQL
    // trans ldmatrix for V: lane -> kv row, d-block
    const uint32_t lmV = (uint32_t)(((lane >> 3) & 1) * 8 + (lane & 7)) * FPITCH
                         + (lane >> 4) * 16;

    for (int t = 0; t < 32; t++) {
        const int cur = t & 1;
        const uint32_t stg = sbase + FSTG0 + (uint32_t)cur * FSTAGE;

        // ---- S = Q K^T (bf16x3), S in fp32 C-frags sc[8][4] ----
        float sc[8][4];
#pragma unroll
        for (int nf = 0; nf < 8; nf++)
#pragma unroll
            for (int k = 0; k < 4; k++) sc[nf][k] = 0.0f;

#pragma unroll
        for (int ks = 0; ks < 8; ks++) {
            uint32_t qh[4], ql[4];
            ldsm4(qAdr + FQH + ks * 32, qh[0], qh[1], qh[2], qh[3]);
            ldsm4(qAdr + FQL + ks * 32, ql[0], ql[1], ql[2], ql[3]);
#pragma unroll
            for (int nfp = 0; nfp < 4; nfp++) {
                uint32_t kAdr = stg + (uint32_t)(nfp * 16) * FPITCH + lmA + ks * 32;
                uint32_t kh0, kh1, kh2, kh3, kl0, kl1, kl2, kl3;
                ldsm4(kAdr + FKH, kh0, kh1, kh2, kh3);
                ldsm4(kAdr + FKL, kl0, kl1, kl2, kl3);
                mma_bf16_2(sc[nfp * 2],     qh, kh0, kh2);
                mma_bf16_2(sc[nfp * 2 + 1], qh, kh1, kh3);
                mma_bf16_2(sc[nfp * 2],     qh, kl0, kl2);
                mma_bf16_2(sc[nfp * 2 + 1], qh, kl1, kl3);
                mma_bf16_2(sc[nfp * 2],     ql, kh0, kh2);
                mma_bf16_2(sc[nfp * 2 + 1], ql, kh1, kh3);
            }
        }

        // ---- online softmax (rows g and g+8) ----
        float mx0 = -INFINITY, mx1 = -INFINITY;
#pragma unroll
        for (int nf = 0; nf < 8; nf++) {
            mx0 = fmaxf(mx0, fmaxf(sc[nf][0], sc[nf][1]));
            mx1 = fmaxf(mx1, fmaxf(sc[nf][2], sc[nf][3]));
        }
        mx0 = fmaxf(mx0, __shfl_xor_sync(0xffffffffu, mx0, 1));
        mx0 = fmaxf(mx0, __shfl_xor_sync(0xffffffffu, mx0, 2));
        mx1 = fmaxf(mx1, __shfl_xor_sync(0xffffffffu, mx1, 1));
        mx1 = fmaxf(mx1, __shfl_xor_sync(0xffffffffu, mx1, 2));

        float mn0 = fmaxf(m0, mx0), mn1 = fmaxf(m1, mx1);
        float a0 = __expf(m0 - mn0), a1 = __expf(m1 - mn1);
        float rs0 = 0.0f, rs1 = 0.0f;
#pragma unroll
        for (int nf = 0; nf < 8; nf++) {
            sc[nf][0] = __expf(sc[nf][0] - mn0);
            sc[nf][1] = __expf(sc[nf][1] - mn0);
            sc[nf][2] = __expf(sc[nf][2] - mn1);
            sc[nf][3] = __expf(sc[nf][3] - mn1);
            rs0 += sc[nf][0] + sc[nf][1];
            rs1 += sc[nf][2] + sc[nf][3];
        }
        rs0 += __shfl_xor_sync(0xffffffffu, rs0, 1);
        rs0 += __shfl_xor_sync(0xffffffffu, rs0, 2);
        rs1 += __shfl_xor_sync(0xffffffffu, rs1, 1);
        rs1 += __shfl_xor_sync(0xffffffffu, rs1, 2);
        l0s = l0s * a0 + rs0;
        l1s = l1s * a1 + rs1;
        m0 = mn0; m1 = mn1;
#pragma unroll
        for (int nf = 0; nf < 16; nf++) {
            o[nf][0] *= a0; o[nf][1] *= a0;
            o[nf][2] *= a1; o[nf][3] *= a1;
        }

        // ---- P -> bf16 hi/lo A-frags (no shuffles: C layout == A sub-layout)
        uint32_t ph[4][4], pl[4][4];
#pragma unroll
        for (int ks = 0; ks < 4; ks++) {
            split2(sc[2 * ks][0],     sc[2 * ks][1],     ph[ks][0], pl[ks][0]);
            split2(sc[2 * ks][2],     sc[2 * ks][3],     ph[ks][1], pl[ks][1]);
            split2(sc[2 * ks + 1][0], sc[2 * ks + 1][1], ph[ks][2], pl[ks][2]);
            split2(sc[2 * ks + 1][2], sc[2 * ks + 1][3], ph[ks][3], pl[ks][3]);
        }

        // ---- O += P V (bf16x3), V via ldmatrix.trans ----
#pragma unroll
        for (int nfp = 0; nfp < 8; nfp++) {
#pragma unroll
            for (int ks = 0; ks < 4; ks++) {
                uint32_t vAdr = stg + (uint32_t)(ks * 16) * FPITCH + lmV + nfp * 32;
                uint32_t vh0, vh1, vh2, vh3, vl0, vl1, vl2, vl3;
                ldsm4t(vAdr + FVH, vh0, vh1, vh2, vh3);
                ldsm4t(vAdr + FVL, vl0, vl1, vl2, vl3);
                mma_bf16_2(o[nfp * 2],     ph[ks], vh0, vh1);
                mma_bf16_2(o[nfp * 2 + 1], ph[ks], vh2, vh3);
                mma_bf16_2(o[nfp * 2],     ph[ks], vl0, vl1);
                mma_bf16_2(o[nfp * 2 + 1], ph[ks], vl2, vl3);
                mma_bf16_2(o[nfp * 2],     pl[ks], vh0, vh1);
                mma_bf16_2(o[nfp * 2 + 1], pl[ks], vh2, vh3);
            }
        }

        // ---- prefetch next tile ----
        if (t + 1 < 32) LOADKV(t + 1, 1 - cur);
        __syncthreads();
    }

    // ---- normalize + store ----
    const float inv0 = 1.0f / l0s;
    const float inv1 = 1.0f / l1s;
    const int g = lane >> 2;
    const int tq = lane & 3;
    const int row0 = q0 + w * 16 + g;
    size_t base0 = ((size_t)(b * SEQ + row0)) * DIM + hoff + tq * 2;
    size_t base1 = base0 + (size_t)8 * DIM;
#pragma unroll
    for (int nf = 0; nf < 16; nf++) {
        *(float2*)&g_attn[base0 + nf * 8] = make_float2(o[nf][0] * inv0,
                                                        o[nf][1] * inv0);
        *(float2*)&g_attn[base1 + nf * 8] = make_float2(o[nf][2] * inv1,
                                                        o[nf][3] * inv1);
    }
#undef LOADKV
}

// ---------------------------------------------------------------------------
// Launch
// ---------------------------------------------------------------------------
extern "C" void kernel_launch(void* const* d_in, const int* in_sizes, int n_in,
                              void* d_out, int out_size) {
    const float* x    = (const float*)d_in[0];
    const float* wq   = (const float*)d_in[1];
    const float* wk   = (const float*)d_in[2];
    const float* wv   = (const float*)d_in[3];
    const float* wo   = (const float*)d_in[4];
    const float* fcos = (const float*)d_in[5];
    const float* fsin = (const float*)d_in[6];
    float* out = (float*)d_out;

    float *qp, *kp, *vp, *ap;
    cudaGetSymbolAddress((void**)&qp, g_q);
    cudaGetSymbolAddress((void**)&kp, g_k);
    cudaGetSymbolAddress((void**)&vp, g_v);
    cudaGetSymbolAddress((void**)&ap, g_attn);

    cudaFuncSetAttribute(gemm_bf16x3, cudaFuncAttributeMaxDynamicSharedMemorySize,
                         GEMM_SMEM);
    cudaFuncSetAttribute(flash_mma, cudaFuncAttributeMaxDynamicSharedMemorySize,
                         FLASH_SMEM);

    dim3 ggrid(DIM / BN, MROWS / BM);   // (32, 32)

    gemm_bf16x3<<<ggrid, 256, GEMM_SMEM>>>(x, wq, qp);
    gemm_bf16x3<<<ggrid, 256, GEMM_SMEM>>>(x, wk, kp);
    gemm_bf16x3<<<ggrid, 256, GEMM_SMEM>>>(x, wv, vp);

    rope_kernel<<<(BATCH * SEQ * NHEAD * 64) / 256, 256>>>(fcos, fsin);

    flash_mma<<<dim3(SEQ / 128, NHEAD, BATCH), 256, FLASH_SMEM>>>();

    gemm_bf16x3<<<ggrid, 256, GEMM_SMEM>>>(ap, wo, out);
}

// round 5
// speedup vs baseline: 2.2627x; 1.1366x over previous
#include <cuda_runtime.h>
#include <cuda_bf16.h>
#include <math.h>
#include <stdint.h>

// Problem constants
#define BATCH 2
#define SEQ   2048
#define DIM   4096
#define NHEAD 32
#define HDIM  128
#define MROWS (BATCH * SEQ)   // 4096
#define NELEM (MROWS * DIM)   // 16777216

// fp32 scratch (GEMM outputs, rope inputs)
__device__ float g_q[NELEM];
__device__ float g_k[NELEM];
__device__ float g_v[NELEM];
// pre-split bf16 scratch
__device__ __nv_bfloat16 g_xh[NELEM],  g_xl[NELEM];
__device__ __nv_bfloat16 g_wqh[NELEM], g_wql[NELEM];
__device__ __nv_bfloat16 g_wkh[NELEM], g_wkl[NELEM];
__device__ __nv_bfloat16 g_wvh[NELEM], g_wvl[NELEM];
__device__ __nv_bfloat16 g_woh[NELEM], g_wol[NELEM];
__device__ __nv_bfloat16 g_qh[NELEM],  g_ql[NELEM];
__device__ __nv_bfloat16 g_kh[NELEM],  g_kl[NELEM];
__device__ __nv_bfloat16 g_vh[NELEM],  g_vl[NELEM];
__device__ __nv_bfloat16 g_ah[NELEM],  g_al[NELEM];

// ---------------------------------------------------------------------------
// Helpers (baseline PTX only — harness targets compute_103)
// ---------------------------------------------------------------------------
__device__ __forceinline__ uint32_t smem_u32(const void* p) {
    uint32_t a;
    asm("{ .reg .u64 t; cvta.to.shared.u64 t, %1; cvt.u32.u64 %0, t; }"
        : "=r"(a) : "l"(p));
    return a;
}

__device__ __forceinline__ void cpa16(uint32_t dst, const void* src) {
    asm volatile("cp.async.cg.shared.global [%0], [%1], 16;"
                 :: "r"(dst), "l"(src));
}
#define CP_COMMIT() asm volatile("cp.async.commit_group;" ::: "memory")
#define CP_WAIT(n)  asm volatile("cp.async.wait_group " #n ";" ::: "memory")

__device__ __forceinline__ void ldsm4(uint32_t addr, uint32_t& r0, uint32_t& r1,
                                      uint32_t& r2, uint32_t& r3) {
    asm volatile("ldmatrix.sync.aligned.m8n8.x4.shared.b16 {%0,%1,%2,%3}, [%4];"
                 : "=r"(r0), "=r"(r1), "=r"(r2), "=r"(r3) : "r"(addr));
}
__device__ __forceinline__ void ldsm4t(uint32_t addr, uint32_t& r0, uint32_t& r1,
                                       uint32_t& r2, uint32_t& r3) {
    asm volatile("ldmatrix.sync.aligned.m8n8.x4.trans.shared.b16 {%0,%1,%2,%3}, [%4];"
                 : "=r"(r0), "=r"(r1), "=r"(r2), "=r"(r3) : "r"(addr));
}

__device__ __forceinline__ void mma_bf16(float* c, const uint32_t* a,
                                         const uint32_t* b) {
    asm volatile(
        "mma.sync.aligned.m16n8k16.row.col.f32.bf16.bf16.f32 "
        "{%0,%1,%2,%3}, {%4,%5,%6,%7}, {%8,%9}, {%0,%1,%2,%3};"
        : "+f"(c[0]), "+f"(c[1]), "+f"(c[2]), "+f"(c[3])
        : "r"(a[0]), "r"(a[1]), "r"(a[2]), "r"(a[3]), "r"(b[0]), "r"(b[1]));
}
__device__ __forceinline__ void mma_bf16_2(float* c, const uint32_t* a,
                                           uint32_t b0, uint32_t b1) {
    asm volatile(
        "mma.sync.aligned.m16n8k16.row.col.f32.bf16.bf16.f32 "
        "{%0,%1,%2,%3}, {%4,%5,%6,%7}, {%8,%9}, {%0,%1,%2,%3};"
        : "+f"(c[0]), "+f"(c[1]), "+f"(c[2]), "+f"(c[3])
        : "r"(a[0]), "r"(a[1]), "r"(a[2]), "r"(a[3]), "r"(b0), "r"(b1));
}

__device__ __forceinline__ uint32_t packbf(__nv_bfloat16 a, __nv_bfloat16 b) {
    return ((uint32_t)__bfloat16_as_ushort(b) << 16) | __bfloat16_as_ushort(a);
}
__device__ __forceinline__ void split2(float x, float y, uint32_t& hi, uint32_t& lo) {
    __nv_bfloat16 hx = __float2bfloat16(x);
    __nv_bfloat16 hy = __float2bfloat16(y);
    hi = packbf(hx, hy);
    lo = packbf(__float2bfloat16(x - __bfloat162float(hx)),
                __float2bfloat16(y - __bfloat162float(hy)));
}

// ---------------------------------------------------------------------------
// Split kernel: fp32 tensor -> (hi, lo) bf16 tensors. n4 = n/4.
// ---------------------------------------------------------------------------
__global__ __launch_bounds__(256) void split_kernel(const float* __restrict__ src,
                                                    __nv_bfloat16* __restrict__ dh,
                                                    __nv_bfloat16* __restrict__ dl,
                                                    int n4) {
    int i = blockIdx.x * blockDim.x + threadIdx.x;
    if (i >= n4) return;
    float4 v = ((const float4*)src)[i];
    uint32_t h0, l0, h1, l1;
    split2(v.x, v.y, h0, l0);
    split2(v.z, v.w, h1, l1);
    ((uint2*)dh)[i] = make_uint2(h0, h1);
    ((uint2*)dl)[i] = make_uint2(l0, l1);
}

// ---------------------------------------------------------------------------
// bf16x3-split GEMM v2 (NT): C = A*B^T, A/B pre-split bf16 hi/lo, C fp32.
// 128x128 tile, BK=32, 256 threads (8 warps 2x4), 4-stage cp.async pipeline.
// ---------------------------------------------------------------------------
#define BM 128
#define BN 128
#define BK 32
#define NKC (DIM / BK)   // 128
#define PITCHB 80

#define OFF_AHI 0
#define OFF_ALO 10240
#define OFF_BHI 20480
#define OFF_BLO 30720
#define STAGE_BYTES 40960
#define NSTG 4
#define GEMM_SMEM (NSTG * STAGE_BYTES)   // 163840

__global__ __launch_bounds__(256, 1)
void gemm_bf16x3(const __nv_bfloat16* __restrict__ Ah,
                 const __nv_bfloat16* __restrict__ Al,
                 const __nv_bfloat16* __restrict__ Bh,
                 const __nv_bfloat16* __restrict__ Bl,
                 float* __restrict__ C) {
    extern __shared__ char smem_raw[];
    const uint32_t sbase = smem_u32(smem_raw);
    const int tid  = threadIdx.x;
    const int wid  = tid >> 5;
    const int lane = tid & 31;
    const int wm   = wid >> 2;
    const int wn   = wid & 3;
    const int m0   = blockIdx.y * BM;
    const int n0   = blockIdx.x * BN;

    const char* Ahb = (const char*)(Ah + (size_t)m0 * DIM);
    const char* Alb = (const char*)(Al + (size_t)m0 * DIM);
    const char* Bhb = (const char*)(Bh + (size_t)n0 * DIM);
    const char* Blb = (const char*)(Bl + (size_t)n0 * DIM);

    float acc[4][4][4];
#pragma unroll
    for (int i = 0; i < 4; i++)
#pragma unroll
        for (int j = 0; j < 4; j++)
#pragma unroll
            for (int k = 0; k < 4; k++) acc[i][j][k] = 0.0f;

    // cp.async mapping: 512 segs of 16B per matrix; thread handles tid, tid+256
    const int seg0 = tid;
#define ISSUE(kc, stg)                                                        \
    {                                                                         \
        uint32_t sb = sbase + (uint32_t)(stg) * STAGE_BYTES;                  \
        size_t gk = (size_t)(kc) * 64;                                        \
        _Pragma("unroll")                                                     \
        for (int u = 0; u < 2; u++) {                                         \
            int seg = seg0 + u * 256;                                         \
            int row = seg >> 2;                                               \
            int off = (seg & 3) * 16;                                         \
            uint32_t so = (uint32_t)row * PITCHB + off;                       \
            size_t go = (size_t)row * (DIM * 2) + gk + off;                   \
            cpa16(sb + OFF_AHI + so, Ahb + go);                               \
            cpa16(sb + OFF_ALO + so, Alb + go);                               \
            cpa16(sb + OFF_BHI + so, Bhb + go);                               \
            cpa16(sb + OFF_BLO + so, Blb + go);                               \
        }                                                                     \
        CP_COMMIT();                                                          \
    }

    const uint32_t lm_off = (uint32_t)(lane & 15) * PITCHB + (lane >> 4) * 16;
    const uint32_t aAdr0 = (uint32_t)(wm * 64) * PITCHB + lm_off;
    const uint32_t bAdr0 = (uint32_t)(wn * 32) * PITCHB + lm_off;

    ISSUE(0, 0);
    ISSUE(1, 1);
    ISSUE(2, 2);

    for (int kc = 0; kc < NKC; kc++) {
        CP_WAIT(2);
        __syncthreads();
        if (kc + 3 < NKC) { ISSUE(kc + 3, (kc + 3) & 3); }
        else { CP_COMMIT(); }

        const uint32_t stg = sbase + (uint32_t)(kc & 3) * STAGE_BYTES;
        const uint32_t aHi = stg + OFF_AHI + aAdr0;
        const uint32_t aLo = stg + OFF_ALO + aAdr0;
        const uint32_t bHi = stg + OFF_BHI + bAdr0;
        const uint32_t bLo = stg + OFF_BLO + bAdr0;

#pragma unroll
        for (int s = 0; s < 2; s++) {
            uint32_t aF[4][4], bH[4][2], bL[4][2];
#pragma unroll
            for (int mi = 0; mi < 4; mi++)
                ldsm4(aHi + mi * (16 * PITCHB) + s * 32,
                      aF[mi][0], aF[mi][1], aF[mi][2], aF[mi][3]);
#pragma unroll
            for (int nj = 0; nj < 2; nj++) {
                uint32_t r0, r1, r2, r3;
                ldsm4(bHi + nj * (16 * PITCHB) + s * 32, r0, r1, r2, r3);
                bH[nj * 2][0] = r0; bH[nj * 2 + 1][0] = r1;
                bH[nj * 2][1] = r2; bH[nj * 2 + 1][1] = r3;
                ldsm4(bLo + nj * (16 * PITCHB) + s * 32, r0, r1, r2, r3);
                bL[nj * 2][0] = r0; bL[nj * 2 + 1][0] = r1;
                bL[nj * 2][1] = r2; bL[nj * 2 + 1][1] = r3;
            }
#pragma unroll
            for (int mi = 0; mi < 4; mi++)
#pragma unroll
                for (int nf = 0; nf < 4; nf++)
                    mma_bf16(acc[mi][nf], aF[mi], bH[nf]);
#pragma unroll
            for (int mi = 0; mi < 4; mi++)
#pragma unroll
                for (int nf = 0; nf < 4; nf++)
                    mma_bf16(acc[mi][nf], aF[mi], bL[nf]);
#pragma unroll
            for (int mi = 0; mi < 4; mi++)
                ldsm4(aLo + mi * (16 * PITCHB) + s * 32,
                      aF[mi][0], aF[mi][1], aF[mi][2], aF[mi][3]);
#pragma unroll
            for (int mi = 0; mi < 4; mi++)
#pragma unroll
                for (int nf = 0; nf < 4; nf++)
                    mma_bf16(acc[mi][nf], aF[mi], bH[nf]);
        }
        __syncthreads();
    }

#pragma unroll
    for (int mi = 0; mi < 4; mi++) {
#pragma unroll
        for (int nf = 0; nf < 4; nf++) {
            int row = m0 + wm * 64 + mi * 16 + (lane >> 2);
            int col = n0 + wn * 32 + nf * 8 + (lane & 3) * 2;
            *(float2*)&C[(size_t)row * DIM + col] =
                make_float2(acc[mi][nf][0], acc[mi][nf][1]);
            *(float2*)&C[(size_t)(row + 8) * DIM + col] =
                make_float2(acc[mi][nf][2], acc[mi][nf][3]);
        }
    }
#undef ISSUE
}

// ---------------------------------------------------------------------------
// RoPE + split: reads fp32 g_q/g_k/g_v, applies rope (q,k) + q-scaling,
// writes bf16 hi/lo arrays for flash.
// ---------------------------------------------------------------------------
__global__ __launch_bounds__(256) void rope_split_kernel(
    const float* __restrict__ fcos, const float* __restrict__ fsin) {
    int idx = blockIdx.x * blockDim.x + threadIdx.x;  // 2^23
    int j = idx & 63;
    int h = (idx >> 6) & 31;
    int s = (idx >> 11) & 2047;
    int b = idx >> 22;
    const float scale = 0.08838834764831845f;  // 1/sqrt(128)

    float c = fcos[s * 64 + j];
    float sn = fsin[s * 64 + j];
    size_t base = ((size_t)(b * SEQ + s)) * DIM + h * HDIM + 2 * j;

    float2 q2 = *(const float2*)&g_q[base];
    float2 k2 = *(const float2*)&g_k[base];
    float2 v2 = *(const float2*)&g_v[base];

    float qr = (q2.x * c - q2.y * sn) * scale;
    float qi = (q2.x * sn + q2.y * c) * scale;
    float kr = k2.x * c - k2.y * sn;
    float ki = k2.x * sn + k2.y * c;

    uint32_t hi, lo;
    split2(qr, qi, hi, lo);
    *(uint32_t*)&g_qh[base] = hi;
    *(uint32_t*)&g_ql[base] = lo;
    split2(kr, ki, hi, lo);
    *(uint32_t*)&g_kh[base] = hi;
    *(uint32_t*)&g_kl[base] = lo;
    split2(v2.x, v2.y, hi, lo);
    *(uint32_t*)&g_vh[base] = hi;
    *(uint32_t*)&g_vl[base] = lo;
}

// ---------------------------------------------------------------------------
// Flash attention v2: pre-split bf16 inputs, cp.async KV pipeline.
// CTA: 128 q-rows of one (b,h); 8 warps x 16 q-rows; 64-kv tiles, 2 stages.
// Writes attn output as pre-split bf16 hi/lo (feeds O-projection GEMM).
// ---------------------------------------------------------------------------
#define FPITCH 272
#define FQH 0
#define FQL (128 * FPITCH)
#define FSTG0 (2 * 128 * FPITCH)
#define FKH 0
#define FKL (64 * FPITCH)
#define FVH (128 * FPITCH)
#define FVL (192 * FPITCH)
#define FSTAGE (256 * FPITCH)            // 69632 per stage
#define FLASH_SMEM (FSTG0 + 2 * FSTAGE)  // 208896

__global__ __launch_bounds__(256)
void flash_mma() {
    extern __shared__ char smem_raw[];
    const uint32_t sbase = smem_u32(smem_raw);
    const int tid  = threadIdx.x;
    const int w    = tid >> 5;
    const int lane = tid & 31;
    const int qt = blockIdx.x;
    const int h  = blockIdx.y;
    const int b  = blockIdx.z;
    const int q0 = qt * 128;
    const size_t hoff = (size_t)h * HDIM;

    const char* khb = (const char*)g_kh;
    const char* klb = (const char*)g_kl;
    const char* vhb = (const char*)g_vh;
    const char* vlb = (const char*)g_vl;

    // ---- Stage Q hi/lo (already roped + scaled) ----
    {
        const char* qhb = (const char*)g_qh;
        const char* qlb = (const char*)g_ql;
        for (int i = tid; i < 2048; i += 256) {
            int r = i >> 4, sg = (i & 15) * 16;
            size_t go = ((size_t)(b * SEQ + q0 + r) * DIM + hoff) * 2 + sg;
            uint32_t so = (uint32_t)r * FPITCH + sg;
            *(uint4*)(smem_raw + FQH + so) = *(const uint4*)(qhb + go);
            *(uint4*)(smem_raw + FQL + so) = *(const uint4*)(qlb + go);
        }
    }

    // KV tile via cp.async: 1024 segs/matrix, thread does tid+u*256, u<4
#define LOADKV(t, stg)                                                        \
    {                                                                         \
        uint32_t sp = sbase + FSTG0 + (uint32_t)(stg) * FSTAGE;               \
        const int j0 = (t) * 64;                                              \
        _Pragma("unroll")                                                     \
        for (int u = 0; u < 4; u++) {                                         \
            int seg = tid + u * 256;                                          \
            int row = seg >> 4;                                               \
            int off = (seg & 15) * 16;                                        \
            uint32_t so = (uint32_t)row * FPITCH + off;                       \
            size_t go = ((size_t)(b * SEQ + j0 + row) * DIM + hoff) * 2 + off;\
            cpa16(sp + FKH + so, khb + go);                                   \
            cpa16(sp + FKL + so, klb + go);                                   \
            cpa16(sp + FVH + so, vhb + go);                                   \
            cpa16(sp + FVL + so, vlb + go);                                   \
        }                                                                     \
        CP_COMMIT();                                                          \
    }

    LOADKV(0, 0);

    float o[16][4];
#pragma unroll
    for (int nf = 0; nf < 16; nf++)
#pragma unroll
        for (int k = 0; k < 4; k++) o[nf][k] = 0.0f;
    float m0 = -INFINITY, m1 = -INFINITY, l0s = 0.0f, l1s = 0.0f;

    const uint32_t lmA = (uint32_t)(lane & 15) * FPITCH + (lane >> 4) * 16;
    const uint32_t qAdr = sbase + (uint32_t)(w * 16) * FPITCH + lmA;
    const uint32_t lmV = (uint32_t)(((lane >> 3) & 1) * 8 + (lane & 7)) * FPITCH
                         + (lane >> 4) * 16;

    for (int t = 0; t < 32; t++) {
        const int cur = t & 1;
        CP_WAIT(0);
        __syncthreads();
        if (t + 1 < 32) { LOADKV(t + 1, 1 - cur); }

        const uint32_t stg = sbase + FSTG0 + (uint32_t)cur * FSTAGE;

        // ---- S = Q K^T ----
        float sc[8][4];
#pragma unroll
        for (int nf = 0; nf < 8; nf++)
#pragma unroll
            for (int k = 0; k < 4; k++) sc[nf][k] = 0.0f;

#pragma unroll
        for (int ks = 0; ks < 8; ks++) {
            uint32_t qh[4], ql[4];
            ldsm4(qAdr + FQH + ks * 32, qh[0], qh[1], qh[2], qh[3]);
            ldsm4(qAdr + FQL + ks * 32, ql[0], ql[1], ql[2], ql[3]);
#pragma unroll
            for (int nfp = 0; nfp < 4; nfp++) {
                uint32_t kAdr = stg + (uint32_t)(nfp * 16) * FPITCH + lmA + ks * 32;
                uint32_t kh0, kh1, kh2, kh3, kl0, kl1, kl2, kl3;
                ldsm4(kAdr + FKH, kh0, kh1, kh2, kh3);
                ldsm4(kAdr + FKL, kl0, kl1, kl2, kl3);
                mma_bf16_2(sc[nfp * 2],     qh, kh0, kh2);
                mma_bf16_2(sc[nfp * 2 + 1], qh, kh1, kh3);
                mma_bf16_2(sc[nfp * 2],     qh, kl0, kl2);
                mma_bf16_2(sc[nfp * 2 + 1], qh, kl1, kl3);
                mma_bf16_2(sc[nfp * 2],     ql, kh0, kh2);
                mma_bf16_2(sc[nfp * 2 + 1], ql, kh1, kh3);
            }
        }

        // ---- online softmax ----
        float mx0 = -INFINITY, mx1 = -INFINITY;
#pragma unroll
        for (int nf = 0; nf < 8; nf++) {
            mx0 = fmaxf(mx0, fmaxf(sc[nf][0], sc[nf][1]));
            mx1 = fmaxf(mx1, fmaxf(sc[nf][2], sc[nf][3]));
        }
        mx0 = fmaxf(mx0, __shfl_xor_sync(0xffffffffu, mx0, 1));
        mx0 = fmaxf(mx0, __shfl_xor_sync(0xffffffffu, mx0, 2));
        mx1 = fmaxf(mx1, __shfl_xor_sync(0xffffffffu, mx1, 1));
        mx1 = fmaxf(mx1, __shfl_xor_sync(0xffffffffu, mx1, 2));

        float mn0 = fmaxf(m0, mx0), mn1 = fmaxf(m1, mx1);
        float a0 = __expf(m0 - mn0), a1 = __expf(m1 - mn1);
        float rs0 = 0.0f, rs1 = 0.0f;
#pragma unroll
        for (int nf = 0; nf < 8; nf++) {
            sc[nf][0] = __expf(sc[nf][0] - mn0);
            sc[nf][1] = __expf(sc[nf][1] - mn0);
            sc[nf][2] = __expf(sc[nf][2] - mn1);
            sc[nf][3] = __expf(sc[nf][3] - mn1);
            rs0 += sc[nf][0] + sc[nf][1];
            rs1 += sc[nf][2] + sc[nf][3];
        }
        rs0 += __shfl_xor_sync(0xffffffffu, rs0, 1);
        rs0 += __shfl_xor_sync(0xffffffffu, rs0, 2);
        rs1 += __shfl_xor_sync(0xffffffffu, rs1, 1);
        rs1 += __shfl_xor_sync(0xffffffffu, rs1, 2);
        l0s = l0s * a0 + rs0;
        l1s = l1s * a1 + rs1;
        m0 = mn0; m1 = mn1;
#pragma unroll
        for (int nf = 0; nf < 16; nf++) {
            o[nf][0] *= a0; o[nf][1] *= a0;
            o[nf][2] *= a1; o[nf][3] *= a1;
        }

        // ---- P -> bf16 hi/lo A-frags ----
        uint32_t ph[4][4], pl[4][4];
#pragma unroll
        for (int ks = 0; ks < 4; ks++) {
            split2(sc[2 * ks][0],     sc[2 * ks][1],     ph[ks][0], pl[ks][0]);
            split2(sc[2 * ks][2],     sc[2 * ks][3],     ph[ks][1], pl[ks][1]);
            split2(sc[2 * ks + 1][0], sc[2 * ks + 1][1], ph[ks][2], pl[ks][2]);
            split2(sc[2 * ks + 1][2], sc[2 * ks + 1][3], ph[ks][3], pl[ks][3]);
        }

        // ---- O += P V ----
#pragma unroll
        for (int nfp = 0; nfp < 8; nfp++) {
#pragma unroll
            for (int ks = 0; ks < 4; ks++) {
                uint32_t vAdr = stg + (uint32_t)(ks * 16) * FPITCH + lmV + nfp * 32;
                uint32_t vh0, vh1, vh2, vh3, vl0, vl1, vl2, vl3;
                ldsm4t(vAdr + FVH, vh0, vh1, vh2, vh3);
                ldsm4t(vAdr + FVL, vl0, vl1, vl2, vl3);
                mma_bf16_2(o[nfp * 2],     ph[ks], vh0, vh1);
                mma_bf16_2(o[nfp * 2 + 1], ph[ks], vh2, vh3);
                mma_bf16_2(o[nfp * 2],     ph[ks], vl0, vl1);
                mma_bf16_2(o[nfp * 2 + 1], ph[ks], vl2, vl3);
                mma_bf16_2(o[nfp * 2],     pl[ks], vh0, vh1);
                mma_bf16_2(o[nfp * 2 + 1], pl[ks], vh2, vh3);
            }
        }
        __syncthreads();
    }

    // ---- normalize + split-store (feeds O GEMM) ----
    const float inv0 = 1.0f / l0s;
    const float inv1 = 1.0f / l1s;
    const int g = lane >> 2;
    const int tq = lane & 3;
    const int row0 = q0 + w * 16 + g;
    size_t base0 = ((size_t)(b * SEQ + row0)) * DIM + hoff + tq * 2;
    size_t base1 = base0 + (size_t)8 * DIM;
#pragma unroll
    for (int nf = 0; nf < 16; nf++) {
        uint32_t hi, lo;
        split2(o[nf][0] * inv0, o[nf][1] * inv0, hi, lo);
        *(uint32_t*)&g_ah[base0 + nf * 8] = hi;
        *(uint32_t*)&g_al[base0 + nf * 8] = lo;
        split2(o[nf][2] * inv1, o[nf][3] * inv1, hi, lo);
        *(uint32_t*)&g_ah[base1 + nf * 8] = hi;
        *(uint32_t*)&g_al[base1 + nf * 8] = lo;
    }
#undef LOADKV
}

// ---------------------------------------------------------------------------
// Launch
// ---------------------------------------------------------------------------
extern "C" void kernel_launch(void* const* d_in, const int* in_sizes, int n_in,
                              void* d_out, int out_size) {
    const float* x    = (const float*)d_in[0];
    const float* wq   = (const float*)d_in[1];
    const float* wk   = (const float*)d_in[2];
    const float* wv   = (const float*)d_in[3];
    const float* wo   = (const float*)d_in[4];
    const float* fcos = (const float*)d_in[5];
    const float* fsin = (const float*)d_in[6];
    float* out = (float*)d_out;

    float *qp, *kp, *vp;
    cudaGetSymbolAddress((void**)&qp, g_q);
    cudaGetSymbolAddress((void**)&kp, g_k);
    cudaGetSymbolAddress((void**)&vp, g_v);

    __nv_bfloat16 *xh, *xl, *wqh, *wql, *wkh, *wkl, *wvh, *wvl, *woh, *wol;
    __nv_bfloat16 *ah, *al;
    cudaGetSymbolAddress((void**)&xh,  g_xh);
    cudaGetSymbolAddress((void**)&xl,  g_xl);
    cudaGetSymbolAddress((void**)&wqh, g_wqh);
    cudaGetSymbolAddress((void**)&wql, g_wql);
    cudaGetSymbolAddress((void**)&wkh, g_wkh);
    cudaGetSymbolAddress((void**)&wkl, g_wkl);
    cudaGetSymbolAddress((void**)&wvh, g_wvh);
    cudaGetSymbolAddress((void**)&wvl, g_wvl);
    cudaGetSymbolAddress((void**)&woh, g_woh);
    cudaGetSymbolAddress((void**)&wol, g_wol);
    cudaGetSymbolAddress((void**)&ah,  g_ah);
    cudaGetSymbolAddress((void**)&al,  g_al);

    cudaFuncSetAttribute(gemm_bf16x3, cudaFuncAttributeMaxDynamicSharedMemorySize,
                         GEMM_SMEM);
    cudaFuncSetAttribute(flash_mma, cudaFuncAttributeMaxDynamicSharedMemorySize,
                         FLASH_SMEM);

    const int n4 = NELEM / 4;
    const int sblk = (n4 + 255) / 256;
    split_kernel<<<sblk, 256>>>(x,  xh,  xl,  n4);
    split_kernel<<<sblk, 256>>>(wq, wqh, wql, n4);
    split_kernel<<<sblk, 256>>>(wk, wkh, wkl, n4);
    split_kernel<<<sblk, 256>>>(wv, wvh, wvl, n4);
    split_kernel<<<sblk, 256>>>(wo, woh, wol, n4);

    dim3 ggrid(DIM / BN, MROWS / BM);   // (32, 32)
    gemm_bf16x3<<<ggrid, 256, GEMM_SMEM>>>(xh, xl, wqh, wql, qp);
    gemm_bf16x3<<<ggrid, 256, GEMM_SMEM>>>(xh, xl, wkh, wkl, kp);
    gemm_bf16x3<<<ggrid, 256, GEMM_SMEM>>>(xh, xl, wvh, wvl, vp);

    rope_split_kernel<<<(BATCH * SEQ * NHEAD * 64) / 256, 256>>>(fcos, fsin);

    flash_mma<<<dim3(SEQ / 128, NHEAD, BATCH), 256, FLASH_SMEM>>>();

    gemm_bf16x3<<<ggrid, 256, GEMM_SMEM>>>(ah, al, woh, wol, out);
}